// round 5
// baseline (speedup 1.0000x reference)
#include <cuda_runtime.h>

// Problem constants
#define BB 2
#define SS 4096
#define DD 512
#define HH 8
#define DK 64
#define MM (BB * SS)   // 8192 rows

// ---------------------------------------------------------------------------
// Scratch (device globals — no runtime allocation)
// ---------------------------------------------------------------------------
__device__ float g_Q[BB * HH * SS * DK];    // [B,H,S,DK]
__device__ float g_K[BB * HH * SS * DK];
__device__ float g_V[BB * HH * SS * DK];
__device__ float g_att[BB * SS * DD];       // [B,S,D] attention output

// ---------------------------------------------------------------------------
// Tiled SGEMM with bias:  C[i,j] = sum_k A[i,k] * W[j,k] + bias[j]
//   A: [M=8192, K=512] row-major, W: [N=512, K=512] row-major.
//   mode 0/1/2: write into g_Q/g_K/g_V with [B,H,S,DK] remap
//   mode 3    : A := g_att, write plain row-major into Cout
// 64x64 block tile, BK=16, 256 threads, 4x4 micro-tile per thread.
// ---------------------------------------------------------------------------
__global__ __launch_bounds__(256)
void gemm_bias_kernel(const float* __restrict__ A,
                      const float* __restrict__ W,
                      const float* __restrict__ bias,
                      float* __restrict__ Cout,
                      int mode)
{
    __shared__ __align__(16) float As[16][64];
    __shared__ __align__(16) float Bs[16][64];

    const float* Ap = (mode == 3) ? g_att : A;

    const int tid  = threadIdx.x;
    const int tx   = tid & 15;         // 0..15 (cols)
    const int ty   = tid >> 4;         // 0..15 (rows)
    const int bm   = blockIdx.y;       // 0..127
    const int bn   = blockIdx.x;       // 0..7
    const int lrow = tid >> 2;         // 0..63 : loader row
    const int lk4  = (tid & 3) << 2;   // 0,4,8,12 : loader k-group

    float c[4][4] = {};

    const float* Arow = Ap + (size_t)(bm * 64 + lrow) * DD + lk4;
    const float* Wrow = W  + (size_t)(bn * 64 + lrow) * DD + lk4;

    for (int kk = 0; kk < DD; kk += 16) {
        float4 a4 = *(const float4*)(Arow + kk);
        float4 b4 = *(const float4*)(Wrow + kk);
        __syncthreads();   // previous iter's reads done
        As[lk4 + 0][lrow] = a4.x;  As[lk4 + 1][lrow] = a4.y;
        As[lk4 + 2][lrow] = a4.z;  As[lk4 + 3][lrow] = a4.w;
        Bs[lk4 + 0][lrow] = b4.x;  Bs[lk4 + 1][lrow] = b4.y;
        Bs[lk4 + 2][lrow] = b4.z;  Bs[lk4 + 3][lrow] = b4.w;
        __syncthreads();

        #pragma unroll
        for (int k = 0; k < 16; k++) {
            float4 av = *(const float4*)&As[k][ty << 2];
            float4 bv = *(const float4*)&Bs[k][tx << 2];
            c[0][0] += av.x * bv.x; c[0][1] += av.x * bv.y;
            c[0][2] += av.x * bv.z; c[0][3] += av.x * bv.w;
            c[1][0] += av.y * bv.x; c[1][1] += av.y * bv.y;
            c[1][2] += av.y * bv.z; c[1][3] += av.y * bv.w;
            c[2][0] += av.z * bv.x; c[2][1] += av.z * bv.y;
            c[2][2] += av.z * bv.z; c[2][3] += av.z * bv.w;
            c[3][0] += av.w * bv.x; c[3][1] += av.w * bv.y;
            c[3][2] += av.w * bv.z; c[3][3] += av.w * bv.w;
        }
    }

    const int r0 = bm * 64 + (ty << 2);
    const int c0 = bn * 64 + (tx << 2);

    float* qkv = (mode == 0) ? g_Q : (mode == 1) ? g_K : g_V;

    #pragma unroll
    for (int i = 0; i < 4; i++) {
        const int row = r0 + i;
        #pragma unroll
        for (int j = 0; j < 4; j++) {
            const int col = c0 + j;
            float v = c[i][j] + bias[col];
            if (mode < 3) {
                // row -> (b, s), col -> (h, dk); head blocks align with bn*64
                const int b  = row >> 12;          // /4096
                const int s  = row & 4095;
                const int h  = col >> 6;
                const int dk = col & 63;
                qkv[(((size_t)(b * HH + h) << 12) + s) * DK + dk] = v;
            } else {
                Cout[(size_t)row * DD + col] = v;
            }
        }
    }
}

// ---------------------------------------------------------------------------
// Causal flash attention.
// grid = (S/64, H, B), block = 64 threads. Thread t owns query row qt*64+t.
// q[64] and acc[64] live in registers; K/V 64x64 tiles in smem.
// Smem reads are warp-broadcast (all threads read the same K/V row element),
// so the loop is FMA-bound. Online softmax with lazy rescale on new max.
// ---------------------------------------------------------------------------
__global__ __launch_bounds__(64)
void attn_kernel()
{
    __shared__ float4 Ks4[64 * 16];   // 64 keys x 64 floats
    __shared__ float4 Vs4[64 * 16];

    const int t  = threadIdx.x;
    const int qt = (SS / 64 - 1) - blockIdx.x;  // heaviest tiles launch first
    const int h  = blockIdx.y;
    const int b  = blockIdx.z;

    const size_t head_off = (size_t)(b * HH + h) * SS * DK;
    const float* Qb = g_Q + head_off;
    const float* Kb = g_K + head_off;
    const float* Vb = g_V + head_off;

    const int r = qt * 64 + t;

    float4 q[16];
    const float4* qrow = (const float4*)(Qb + (size_t)r * DK);
    #pragma unroll
    for (int i = 0; i < 16; i++) q[i] = qrow[i];

    float4 acc[16];
    #pragma unroll
    for (int i = 0; i < 16; i++) acc[i] = make_float4(0.f, 0.f, 0.f, 0.f);

    float m = -1e30f;
    float l = 0.f;
    const float scale = 0.125f;  // 1/sqrt(64)

    for (int kt = 0; kt <= qt; kt++) {
        __syncthreads();
        const float4* Kg = (const float4*)(Kb + (size_t)kt * 64 * DK);
        const float4* Vg = (const float4*)(Vb + (size_t)kt * 64 * DK);
        #pragma unroll
        for (int u = 0; u < 16; u++) {
            Ks4[u * 64 + t] = Kg[u * 64 + t];
            Vs4[u * 64 + t] = Vg[u * 64 + t];
        }
        __syncthreads();

        const int jmax = (kt == qt) ? (t + 1) : 64;
        for (int j = 0; j < jmax; j++) {
            const float4* kr = &Ks4[j * 16];
            float sx = 0.f, sy = 0.f, sz = 0.f, sw = 0.f;
            #pragma unroll
            for (int i = 0; i < 16; i++) {
                float4 kv = kr[i];
                sx += q[i].x * kv.x;  sy += q[i].y * kv.y;
                sz += q[i].z * kv.z;  sw += q[i].w * kv.w;
            }
            const float s = (sx + sy + sz + sw) * scale;

            float p;
            if (s <= m) {
                p = __expf(s - m);
            } else {
                const float cc = __expf(m - s);   // rare (≈log(S) times/row)
                l *= cc;
                #pragma unroll
                for (int i = 0; i < 16; i++) {
                    acc[i].x *= cc; acc[i].y *= cc;
                    acc[i].z *= cc; acc[i].w *= cc;
                }
                m = s;
                p = 1.f;
            }
            l += p;

            const float4* vr = &Vs4[j * 16];
            #pragma unroll
            for (int i = 0; i < 16; i++) {
                float4 vv = vr[i];
                acc[i].x += p * vv.x;  acc[i].y += p * vv.y;
                acc[i].z += p * vv.z;  acc[i].w += p * vv.w;
            }
        }
    }

    const float inv = 1.f / l;
    float4* orow = (float4*)(g_att + ((size_t)(b * SS + r)) * DD + h * DK);
    #pragma unroll
    for (int i = 0; i < 16; i++) {
        float4 o;
        o.x = acc[i].x * inv;  o.y = acc[i].y * inv;
        o.z = acc[i].z * inv;  o.w = acc[i].w * inv;
        orow[i] = o;
    }
}

// ---------------------------------------------------------------------------
// Launch
// ---------------------------------------------------------------------------
extern "C" void kernel_launch(void* const* d_in, const int* in_sizes, int n_in,
                              void* d_out, int out_size)
{
    const float* x  = (const float*)d_in[0];
    const float* Wq = (const float*)d_in[1];
    const float* bq = (const float*)d_in[2];
    const float* Wk = (const float*)d_in[3];
    const float* bk = (const float*)d_in[4];
    const float* Wv = (const float*)d_in[5];
    const float* bv = (const float*)d_in[6];
    const float* Wo = (const float*)d_in[7];
    const float* bo = (const float*)d_in[8];
    float* out = (float*)d_out;

    dim3 ggrid(DD / 64, MM / 64);   // (8, 128)

    gemm_bias_kernel<<<ggrid, 256>>>(x, Wq, bq, nullptr, 0);
    gemm_bias_kernel<<<ggrid, 256>>>(x, Wk, bk, nullptr, 1);
    gemm_bias_kernel<<<ggrid, 256>>>(x, Wv, bv, nullptr, 2);

    attn_kernel<<<dim3(SS / 64, HH, BB), 64>>>();

    gemm_bias_kernel<<<ggrid, 256>>>(nullptr, Wo, bo, out, 3);
}

// round 6
// speedup vs baseline: 1.0351x; 1.0351x over previous
#include <cuda_runtime.h>

// Problem constants
#define BB 2
#define SS 4096
#define DD 512
#define HH 8
#define DK 64
#define MM (BB * SS)   // 8192 rows

// ---------------------------------------------------------------------------
// Scratch (device globals — no runtime allocation)
// ---------------------------------------------------------------------------
__device__ __align__(16) float g_Q[BB * HH * SS * DK];    // [B,H,S,DK]
__device__ __align__(16) float g_K[BB * HH * SS * DK];
__device__ __align__(16) float g_V[BB * HH * SS * DK];
__device__ __align__(16) float g_att[BB * SS * DD];       // [B,S,D]

// ---------------------------------------------------------------------------
// Packed fp32x2 helpers (sm_103a FFMA2 path — ptxas never emits from C++)
// ---------------------------------------------------------------------------
typedef unsigned long long u64;

__device__ __forceinline__ u64 ffma2(u64 a, u64 b, u64 c) {
    u64 d;
    asm("fma.rn.f32x2 %0, %1, %2, %3;" : "=l"(d) : "l"(a), "l"(b), "l"(c));
    return d;
}
__device__ __forceinline__ u64 fadd2(u64 a, u64 b) {
    u64 d;
    asm("add.rn.f32x2 %0, %1, %2;" : "=l"(d) : "l"(a), "l"(b));
    return d;
}
__device__ __forceinline__ u64 fmul2(u64 a, u64 b) {
    u64 d;
    asm("mul.rn.f32x2 %0, %1, %2;" : "=l"(d) : "l"(a), "l"(b));
    return d;
}
__device__ __forceinline__ u64 pack2(float x) {
    u64 d;
    asm("mov.b64 %0, {%1, %1};" : "=l"(d) : "f"(x));
    return d;
}
__device__ __forceinline__ float2 unpack2(u64 v) {
    float2 r;
    asm("mov.b64 {%0, %1}, %2;" : "=f"(r.x), "=f"(r.y) : "l"(v));
    return r;
}

// ---------------------------------------------------------------------------
// Tiled SGEMM with bias:  C[i,j] = sum_k A[i,k] * W[j,k] + bias[j]
//   A: [8192, 512] row-major, W: [512, 512] row-major.
//   64x128 block tile, BK=16, 256 threads, 4x8 micro-tile, packed FFMA2.
//   mode 0/1/2 -> g_Q/g_K/g_V with [B,H,S,DK] remap; mode 3 -> Cout plain.
// ---------------------------------------------------------------------------
__global__ __launch_bounds__(256)
void gemm_bias_kernel(const float* __restrict__ A,
                      const float* __restrict__ W,
                      const float* __restrict__ bias,
                      float* __restrict__ Cout,
                      int mode)
{
    __shared__ __align__(16) float As[16][64];
    __shared__ __align__(16) float Bs[16][128];

    const float* Ap = (mode == 3) ? g_att : A;

    const int tid = threadIdx.x;
    const int tx  = tid & 15;          // 0..15 -> cols tx*8..+7
    const int ty  = tid >> 4;          // 0..15 -> rows ty*4..+3
    const int bm  = blockIdx.y;        // 0..127
    const int bn  = blockIdx.x;        // 0..3

    // loaders
    const int lrow = tid >> 2;         // 0..63
    const int lk4  = (tid & 3) << 2;   // 0,4,8,12

    const float* Aptr  = Ap + (size_t)(bm * 64 + lrow) * DD + lk4;
    const float* Wptr0 = W  + (size_t)(bn * 128 + lrow) * DD + lk4;
    const float* Wptr1 = Wptr0 + (size_t)64 * DD;

    u64 c[16];                         // c[i*4+jp]: row i, col pair jp
    #pragma unroll
    for (int i = 0; i < 16; i++) c[i] = 0ull;

    for (int kk = 0; kk < DD; kk += 16) {
        float4 a4 = *(const float4*)(Aptr  + kk);
        float4 w0 = *(const float4*)(Wptr0 + kk);
        float4 w1 = *(const float4*)(Wptr1 + kk);
        __syncthreads();
        As[lk4 + 0][lrow] = a4.x;  As[lk4 + 1][lrow] = a4.y;
        As[lk4 + 2][lrow] = a4.z;  As[lk4 + 3][lrow] = a4.w;
        Bs[lk4 + 0][lrow] = w0.x;  Bs[lk4 + 1][lrow] = w0.y;
        Bs[lk4 + 2][lrow] = w0.z;  Bs[lk4 + 3][lrow] = w0.w;
        Bs[lk4 + 0][lrow + 64] = w1.x;  Bs[lk4 + 1][lrow + 64] = w1.y;
        Bs[lk4 + 2][lrow + 64] = w1.z;  Bs[lk4 + 3][lrow + 64] = w1.w;
        __syncthreads();

        #pragma unroll
        for (int k = 0; k < 16; k++) {
            float4 av = *(const float4*)&As[k][ty << 2];
            const u64* bp = (const u64*)&Bs[k][tx << 3];   // 4 packed col-pairs
            u64 b0 = bp[0], b1 = bp[1], b2 = bp[2], b3 = bp[3];
            u64 ax = pack2(av.x), ay = pack2(av.y);
            u64 az = pack2(av.z), aw = pack2(av.w);
            c[0]  = ffma2(ax, b0, c[0]);  c[1]  = ffma2(ax, b1, c[1]);
            c[2]  = ffma2(ax, b2, c[2]);  c[3]  = ffma2(ax, b3, c[3]);
            c[4]  = ffma2(ay, b0, c[4]);  c[5]  = ffma2(ay, b1, c[5]);
            c[6]  = ffma2(ay, b2, c[6]);  c[7]  = ffma2(ay, b3, c[7]);
            c[8]  = ffma2(az, b0, c[8]);  c[9]  = ffma2(az, b1, c[9]);
            c[10] = ffma2(az, b2, c[10]); c[11] = ffma2(az, b3, c[11]);
            c[12] = ffma2(aw, b0, c[12]); c[13] = ffma2(aw, b1, c[13]);
            c[14] = ffma2(aw, b2, c[14]); c[15] = ffma2(aw, b3, c[15]);
        }
    }

    const int r0 = bm * 64 + (ty << 2);
    const int c0 = bn * 128 + (tx << 3);
    float* qkv = (mode == 0) ? g_Q : (mode == 1) ? g_K : g_V;

    #pragma unroll
    for (int i = 0; i < 4; i++) {
        const int row = r0 + i;
        #pragma unroll
        for (int jp = 0; jp < 4; jp++) {
            float2 cv = unpack2(c[i * 4 + jp]);
            const int col0 = c0 + jp * 2;
            float v0 = cv.x + bias[col0];
            float v1 = cv.y + bias[col0 + 1];
            if (mode < 3) {
                const int b = row >> 12;
                const int s = row & 4095;
                const int h = col0 >> 6;          // pair never crosses a head
                const int dk = col0 & 63;
                float* dst = &qkv[(((size_t)(b * HH + h) << 12) + s) * DK + dk];
                dst[0] = v0;  dst[1] = v1;
            } else {
                float* dst = &Cout[(size_t)row * DD + col0];
                dst[0] = v0;  dst[1] = v1;
            }
        }
    }
}

// ---------------------------------------------------------------------------
// Causal flash attention, packed fp32x2.
// grid = (S/128, H, B), block = 128. Thread t owns query row qt*128+t.
// q (32 packed) and acc (32 packed) in registers; 64-key K/V tiles in smem.
// Inner loop unrolled by 2 keys for ILP; lazy rescale on new max.
// ---------------------------------------------------------------------------
__global__ __launch_bounds__(128)
void attn_kernel()
{
    __shared__ __align__(16) u64 Ks[64 * 32];   // 64 keys x 32 packed
    __shared__ __align__(16) u64 Vs[64 * 32];

    const int t  = threadIdx.x;
    const int qt = (SS / 128 - 1) - blockIdx.x;   // heaviest tiles first
    const int h  = blockIdx.y;
    const int b  = blockIdx.z;

    const size_t head_off = (size_t)(b * HH + h) * SS * DK;
    const float* Qb = g_Q + head_off;
    const float* Kb = g_K + head_off;
    const float* Vb = g_V + head_off;

    const int r = qt * 128 + t;

    u64 q[32];
    {
        const ulonglong2* qrow = (const ulonglong2*)(Qb + (size_t)r * DK);
        #pragma unroll
        for (int i = 0; i < 16; i++) { ulonglong2 v = qrow[i]; q[2*i] = v.x; q[2*i+1] = v.y; }
    }

    u64 acc[32];
    #pragma unroll
    for (int i = 0; i < 32; i++) acc[i] = 0ull;

    float m = -1e30f;
    float l = 0.f;
    const float scale = 0.125f;   // 1/sqrt(64)

    const int ntiles = 2 * qt + 2;
    for (int kt = 0; kt < ntiles; kt++) {
        __syncthreads();
        {
            const ulonglong2* Kg = (const ulonglong2*)(Kb + (size_t)kt * 64 * DK);
            const ulonglong2* Vg = (const ulonglong2*)(Vb + (size_t)kt * 64 * DK);
            ulonglong2* Ks2 = (ulonglong2*)Ks;
            ulonglong2* Vs2 = (ulonglong2*)Vs;
            #pragma unroll
            for (int u = 0; u < 8; u++) {
                Ks2[u * 128 + t] = Kg[u * 128 + t];
                Vs2[u * 128 + t] = Vg[u * 128 + t];
            }
        }
        __syncthreads();

        int jmax = r - kt * 64 + 1;
        if (jmax > 64) jmax = 64;

        int j = 0;
        for (; j + 1 < jmax; j += 2) {
            // --- two independent dot products ---
            const ulonglong2* kr0 = (const ulonglong2*)&Ks[(size_t)j * 32];
            const ulonglong2* kr1 = (const ulonglong2*)&Ks[(size_t)(j + 1) * 32];
            u64 d0 = 0, d1 = 0, d2 = 0, d3 = 0;
            u64 e0 = 0, e1 = 0, e2 = 0, e3 = 0;
            #pragma unroll
            for (int i = 0; i < 16; i++) {
                ulonglong2 k0 = kr0[i];
                ulonglong2 k1 = kr1[i];
                if (i & 1) {
                    d2 = ffma2(q[2*i], k0.x, d2);  d3 = ffma2(q[2*i+1], k0.y, d3);
                    e2 = ffma2(q[2*i], k1.x, e2);  e3 = ffma2(q[2*i+1], k1.y, e3);
                } else {
                    d0 = ffma2(q[2*i], k0.x, d0);  d1 = ffma2(q[2*i+1], k0.y, d1);
                    e0 = ffma2(q[2*i], k1.x, e0);  e1 = ffma2(q[2*i+1], k1.y, e1);
                }
            }
            float2 dv = unpack2(fadd2(fadd2(d0, d1), fadd2(d2, d3)));
            float2 ev = unpack2(fadd2(fadd2(e0, e1), fadd2(e2, e3)));
            const float s0 = (dv.x + dv.y) * scale;
            const float s1 = (ev.x + ev.y) * scale;

            // --- online softmax (rescale rare) ---
            const float mx = fmaxf(s0, s1);
            if (mx > m) {
                const float cc = __expf(m - mx);
                l *= cc;
                const u64 ccp = pack2(cc);
                #pragma unroll
                for (int i = 0; i < 32; i++) acc[i] = fmul2(acc[i], ccp);
                m = mx;
            }
            const float p0 = __expf(s0 - m);
            const float p1 = __expf(s1 - m);
            l += p0 + p1;

            const u64 p0p = pack2(p0);
            const u64 p1p = pack2(p1);
            const ulonglong2* v0 = (const ulonglong2*)&Vs[(size_t)j * 32];
            const ulonglong2* v1 = (const ulonglong2*)&Vs[(size_t)(j + 1) * 32];
            #pragma unroll
            for (int i = 0; i < 16; i++) {
                ulonglong2 a = v0[i];
                ulonglong2 bb = v1[i];
                acc[2*i]   = ffma2(p0p, a.x,  acc[2*i]);
                acc[2*i]   = ffma2(p1p, bb.x, acc[2*i]);
                acc[2*i+1] = ffma2(p0p, a.y,  acc[2*i+1]);
                acc[2*i+1] = ffma2(p1p, bb.y, acc[2*i+1]);
            }
        }
        if (j < jmax) {   // remainder key
            const ulonglong2* kr0 = (const ulonglong2*)&Ks[(size_t)j * 32];
            u64 d0 = 0, d1 = 0, d2 = 0, d3 = 0;
            #pragma unroll
            for (int i = 0; i < 16; i++) {
                ulonglong2 k0 = kr0[i];
                if (i & 1) { d2 = ffma2(q[2*i], k0.x, d2);  d3 = ffma2(q[2*i+1], k0.y, d3); }
                else       { d0 = ffma2(q[2*i], k0.x, d0);  d1 = ffma2(q[2*i+1], k0.y, d1); }
            }
            float2 dv = unpack2(fadd2(fadd2(d0, d1), fadd2(d2, d3)));
            const float s0 = (dv.x + dv.y) * scale;

            float p0;
            if (s0 <= m) {
                p0 = __expf(s0 - m);
            } else {
                const float cc = __expf(m - s0);
                l *= cc;
                const u64 ccp = pack2(cc);
                #pragma unroll
                for (int i = 0; i < 32; i++) acc[i] = fmul2(acc[i], ccp);
                m = s0;
                p0 = 1.f;
            }
            l += p0;

            const u64 p0p = pack2(p0);
            const ulonglong2* v0 = (const ulonglong2*)&Vs[(size_t)j * 32];
            #pragma unroll
            for (int i = 0; i < 16; i++) {
                ulonglong2 a = v0[i];
                acc[2*i]   = ffma2(p0p, a.x, acc[2*i]);
                acc[2*i+1] = ffma2(p0p, a.y, acc[2*i+1]);
            }
        }
    }

    const float inv = 1.f / l;
    const u64 invp = pack2(inv);
    ulonglong2* orow = (ulonglong2*)(g_att + ((size_t)(b * SS + r)) * DD + h * DK);
    #pragma unroll
    for (int i = 0; i < 16; i++) {
        ulonglong2 o;
        o.x = fmul2(acc[2*i],   invp);
        o.y = fmul2(acc[2*i+1], invp);
        orow[i] = o;
    }
}

// ---------------------------------------------------------------------------
// Launch
// ---------------------------------------------------------------------------
extern "C" void kernel_launch(void* const* d_in, const int* in_sizes, int n_in,
                              void* d_out, int out_size)
{
    const float* x  = (const float*)d_in[0];
    const float* Wq = (const float*)d_in[1];
    const float* bq = (const float*)d_in[2];
    const float* Wk = (const float*)d_in[3];
    const float* bk = (const float*)d_in[4];
    const float* Wv = (const float*)d_in[5];
    const float* bv = (const float*)d_in[6];
    const float* Wo = (const float*)d_in[7];
    const float* bo = (const float*)d_in[8];
    float* out = (float*)d_out;

    dim3 ggrid(DD / 128, MM / 64);   // (4, 128)

    gemm_bias_kernel<<<ggrid, 256>>>(x, Wq, bq, nullptr, 0);
    gemm_bias_kernel<<<ggrid, 256>>>(x, Wk, bk, nullptr, 1);
    gemm_bias_kernel<<<ggrid, 256>>>(x, Wv, bv, nullptr, 2);

    attn_kernel<<<dim3(SS / 128, HH, BB), 128>>>();

    gemm_bias_kernel<<<ggrid, 256>>>(nullptr, Wo, bo, out, 3);
}

// round 8
// speedup vs baseline: 1.1436x; 1.1048x over previous
#include <cuda_runtime.h>

// Problem constants
#define BB 2
#define SS 4096
#define DD 512
#define HH 8
#define DK 64
#define MM (BB * SS)   // 8192 rows
#define QT 128         // q rows per attention block
#define KT 64          // k cols per attention tile

// ---------------------------------------------------------------------------
// Scratch (device globals — no runtime allocation)
// g_Qt / g_Kt are TRANSPOSED per head: [b][h][dk][s]  (dk-major)
// g_V natural: [b][h][s][dk]
// ---------------------------------------------------------------------------
__device__ __align__(16) float g_Qt[BB * HH * DK * SS];
__device__ __align__(16) float g_Kt[BB * HH * DK * SS];
__device__ __align__(16) float g_V [BB * HH * SS * DK];
__device__ __align__(16) float g_att[BB * SS * DD];       // [B,S,D]

// ---------------------------------------------------------------------------
// Packed fp32x2 helpers
// ---------------------------------------------------------------------------
typedef unsigned long long u64;

__device__ __forceinline__ u64 ffma2(u64 a, u64 b, u64 c) {
    u64 d;
    asm("fma.rn.f32x2 %0, %1, %2, %3;" : "=l"(d) : "l"(a), "l"(b), "l"(c));
    return d;
}
__device__ __forceinline__ u64 fmul2(u64 a, u64 b) {
    u64 d;
    asm("mul.rn.f32x2 %0, %1, %2;" : "=l"(d) : "l"(a), "l"(b));
    return d;
}
__device__ __forceinline__ u64 pack2(float x) {
    u64 d;
    asm("mov.b64 %0, {%1, %1};" : "=l"(d) : "f"(x));
    return d;
}
__device__ __forceinline__ u64 packpair(float a, float b) {
    u64 d;
    asm("mov.b64 %0, {%1, %2};" : "=l"(d) : "f"(a), "f"(b));
    return d;
}
__device__ __forceinline__ float2 unpack2(u64 v) {
    float2 r;
    asm("mov.b64 {%0, %1}, %2;" : "=f"(r.x), "=f"(r.y) : "l"(v));
    return r;
}

// ---------------------------------------------------------------------------
// Tiled SGEMM with bias:  C[i,j] = sum_k A[i,k] * W[j,k] + bias[j]
//   mode 0/1: write TRANSPOSED into g_Qt/g_Kt  ([b][h][dk][s])
//   mode 2  : write natural into g_V           ([b][h][s][dk])
//   mode 3  : A := g_att, plain row-major into Cout
// ---------------------------------------------------------------------------
__global__ __launch_bounds__(256)
void gemm_bias_kernel(const float* __restrict__ A,
                      const float* __restrict__ W,
                      const float* __restrict__ bias,
                      float* __restrict__ Cout,
                      int mode)
{
    __shared__ __align__(16) float As[16][64];
    __shared__ __align__(16) float Bs[16][128];

    const float* Ap = (mode == 3) ? g_att : A;

    const int tid = threadIdx.x;
    const int tx  = tid & 15;
    const int ty  = tid >> 4;
    const int bm  = blockIdx.y;
    const int bn  = blockIdx.x;

    const int lrow = tid >> 2;
    const int lk4  = (tid & 3) << 2;

    const float* Aptr  = Ap + (size_t)(bm * 64 + lrow) * DD + lk4;
    const float* Wptr0 = W  + (size_t)(bn * 128 + lrow) * DD + lk4;
    const float* Wptr1 = Wptr0 + (size_t)64 * DD;

    u64 c[16];
    #pragma unroll
    for (int i = 0; i < 16; i++) c[i] = 0ull;

    for (int kk = 0; kk < DD; kk += 16) {
        float4 a4 = *(const float4*)(Aptr  + kk);
        float4 w0 = *(const float4*)(Wptr0 + kk);
        float4 w1 = *(const float4*)(Wptr1 + kk);
        __syncthreads();
        As[lk4 + 0][lrow] = a4.x;  As[lk4 + 1][lrow] = a4.y;
        As[lk4 + 2][lrow] = a4.z;  As[lk4 + 3][lrow] = a4.w;
        Bs[lk4 + 0][lrow] = w0.x;  Bs[lk4 + 1][lrow] = w0.y;
        Bs[lk4 + 2][lrow] = w0.z;  Bs[lk4 + 3][lrow] = w0.w;
        Bs[lk4 + 0][lrow + 64] = w1.x;  Bs[lk4 + 1][lrow + 64] = w1.y;
        Bs[lk4 + 2][lrow + 64] = w1.z;  Bs[lk4 + 3][lrow + 64] = w1.w;
        __syncthreads();

        #pragma unroll
        for (int k = 0; k < 16; k++) {
            float4 av = *(const float4*)&As[k][ty << 2];
            const u64* bp = (const u64*)&Bs[k][tx << 3];
            u64 b0 = bp[0], b1 = bp[1], b2 = bp[2], b3 = bp[3];
            u64 ax = pack2(av.x), ay = pack2(av.y);
            u64 az = pack2(av.z), aw = pack2(av.w);
            c[0]  = ffma2(ax, b0, c[0]);  c[1]  = ffma2(ax, b1, c[1]);
            c[2]  = ffma2(ax, b2, c[2]);  c[3]  = ffma2(ax, b3, c[3]);
            c[4]  = ffma2(ay, b0, c[4]);  c[5]  = ffma2(ay, b1, c[5]);
            c[6]  = ffma2(ay, b2, c[6]);  c[7]  = ffma2(ay, b3, c[7]);
            c[8]  = ffma2(az, b0, c[8]);  c[9]  = ffma2(az, b1, c[9]);
            c[10] = ffma2(az, b2, c[10]); c[11] = ffma2(az, b3, c[11]);
            c[12] = ffma2(aw, b0, c[12]); c[13] = ffma2(aw, b1, c[13]);
            c[14] = ffma2(aw, b2, c[14]); c[15] = ffma2(aw, b3, c[15]);
        }
    }

    const int r0 = bm * 64 + (ty << 2);
    const int c0 = bn * 128 + (tx << 3);
    float* qkv = (mode == 0) ? g_Qt : (mode == 1) ? g_Kt : g_V;

    #pragma unroll
    for (int i = 0; i < 4; i++) {
        const int row = r0 + i;
        #pragma unroll
        for (int jp = 0; jp < 4; jp++) {
            float2 cv = unpack2(c[i * 4 + jp]);
            const int col0 = c0 + jp * 2;
            float v0 = cv.x + bias[col0];
            float v1 = cv.y + bias[col0 + 1];
            if (mode < 2) {
                // transposed: [b][h][dk][s]
                const int b  = row >> 12;
                const int s  = row & 4095;
                const int h  = col0 >> 6;
                const int dk = col0 & 63;
                float* base = &qkv[((size_t)(b * HH + h) * DK + dk) * SS + s];
                base[0]  = v0;
                base[SS] = v1;
            } else if (mode == 2) {
                const int b  = row >> 12;
                const int s  = row & 4095;
                const int h  = col0 >> 6;
                const int dk = col0 & 63;
                float* dst = &qkv[(((size_t)(b * HH + h) << 12) + s) * DK + dk];
                dst[0] = v0;  dst[1] = v1;
            } else {
                float* dst = &Cout[(size_t)row * DD + col0];
                dst[0] = v0;  dst[1] = v1;
            }
        }
    }
}

// ---------------------------------------------------------------------------
// Register-tiled causal flash attention.
// Block 256 thr (tx 0..15, ty 0..15). Q-tile 128 rows, K-tile 64 cols.
// Thread micro-tile: 8 rows (ty*8..) x 4 cols (tx*4..), packed over row-pairs.
// ---------------------------------------------------------------------------
#define QS_STRIDE 132
#define KS_STRIDE 68
#define PS_STRIDE 68
#define SMEM_ATTN ((64 * QS_STRIDE + 64 * KS_STRIDE + 64 * KS_STRIDE + 128 * PS_STRIDE) * 4)

__global__ __launch_bounds__(256, 2)
void attn_kernel()
{
    extern __shared__ float sm[];
    float* Qs = sm;                          // [64][132]  Qs[dk][r]
    float* Ks = Qs + 64 * QS_STRIDE;         // [64][68]   Ks[dk][j]
    float* Vs = Ks + 64 * KS_STRIDE;         // [64][68]   Vs[j][d]
    float* Ps = Vs + 64 * KS_STRIDE;         // [128][68]  Ps[r][j]

    const int tid = threadIdx.x;
    const int tx  = tid & 15;
    const int ty  = tid >> 4;
    const int qt  = (SS / QT - 1) - blockIdx.x;   // heaviest first
    const int h   = blockIdx.y;
    const int b   = blockIdx.z;

    const size_t ho_t = (size_t)(b * HH + h) * DK * SS;   // Qt/Kt base
    const size_t ho_v = (size_t)(b * HH + h) * SS * DK;   // V base

    // ---- stage Q tile: 64 dk x 128 rows = 2048 float4 -> 8 iterations ----
    #pragma unroll
    for (int u = 0; u < 8; u++) {
        const int idx = u * 256 + tid;
        const int dk  = idx >> 5;       // 0..63
        const int rg  = idx & 31;       // float4 group 0..31
        float4 v = *(const float4*)(g_Qt + ho_t + (size_t)dk * SS + qt * QT + rg * 4);
        *(float4*)&Qs[dk * QS_STRIDE + rg * 4] = v;
    }

    u64 acc2[4][4];
    #pragma unroll
    for (int i = 0; i < 4; i++)
        #pragma unroll
        for (int j = 0; j < 4; j++) acc2[i][j] = 0ull;

    float m[8], l[8];
    #pragma unroll
    for (int r = 0; r < 8; r++) { m[r] = -1e30f; l[r] = 0.f; }

    const float scale = 0.125f;   // 1/sqrt(64)
    const int ntiles = 2 * qt + 2;

    for (int kt = 0; kt < ntiles; kt++) {
        __syncthreads();
        // ---- stage K (transposed source) and V tiles ----
        #pragma unroll
        for (int u = 0; u < 4; u++) {
            const int idx = u * 256 + tid;
            const int row = idx >> 4;       // 0..63
            const int g4  = idx & 15;       // float4 group 0..15
            float4 kv = *(const float4*)(g_Kt + ho_t + (size_t)row * SS + kt * KT + g4 * 4);
            *(float4*)&Ks[row * KS_STRIDE + g4 * 4] = kv;
            float4 vv = *(const float4*)(g_V + ho_v + (size_t)(kt * KT + row) * DK + g4 * 4);
            *(float4*)&Vs[row * KS_STRIDE + g4 * 4] = vv;
        }
        __syncthreads();

        // ---- QK^T: 8x4 score micro-tile, packed over row pairs ----
        u64 s2[4][4];
        #pragma unroll
        for (int i = 0; i < 4; i++)
            #pragma unroll
            for (int j = 0; j < 4; j++) s2[i][j] = 0ull;

        const float* QsT = Qs + ty * 8;
        const float* KsT = Ks + tx * 4;
        #pragma unroll 8
        for (int dk = 0; dk < 64; dk++) {
            const u64* q2 = (const u64*)(QsT + dk * QS_STRIDE);
            const u64 qa = q2[0], qb = q2[1], qc = q2[2], qd = q2[3];
            float4 kv = *(const float4*)(KsT + dk * KS_STRIDE);
            const u64 k0 = pack2(kv.x), k1 = pack2(kv.y);
            const u64 k2 = pack2(kv.z), k3 = pack2(kv.w);
            s2[0][0] = ffma2(qa, k0, s2[0][0]);  s2[0][1] = ffma2(qa, k1, s2[0][1]);
            s2[0][2] = ffma2(qa, k2, s2[0][2]);  s2[0][3] = ffma2(qa, k3, s2[0][3]);
            s2[1][0] = ffma2(qb, k0, s2[1][0]);  s2[1][1] = ffma2(qb, k1, s2[1][1]);
            s2[1][2] = ffma2(qb, k2, s2[1][2]);  s2[1][3] = ffma2(qb, k3, s2[1][3]);
            s2[2][0] = ffma2(qc, k0, s2[2][0]);  s2[2][1] = ffma2(qc, k1, s2[2][1]);
            s2[2][2] = ffma2(qc, k2, s2[2][2]);  s2[2][3] = ffma2(qc, k3, s2[2][3]);
            s2[3][0] = ffma2(qd, k0, s2[3][0]);  s2[3][1] = ffma2(qd, k1, s2[3][1]);
            s2[3][2] = ffma2(qd, k2, s2[3][2]);  s2[3][3] = ffma2(qd, k3, s2[3][3]);
        }

        // ---- unpack scores, scale, causal mask ----
        float p[8][4];
        #pragma unroll
        for (int rp = 0; rp < 4; rp++)
            #pragma unroll
            for (int c = 0; c < 4; c++) {
                float2 v = unpack2(s2[rp][c]);
                p[2 * rp][c]     = v.x * scale;
                p[2 * rp + 1][c] = v.y * scale;
            }

        if (kt >= 2 * qt) {   // diagonal tiles only
            const int rbase = qt * QT + ty * 8 - kt * KT;   // row - tile col origin
            #pragma unroll
            for (int r = 0; r < 8; r++) {
                const int lim = rbase + r;                   // local col limit
                #pragma unroll
                for (int c = 0; c < 4; c++)
                    if (tx * 4 + c > lim) p[r][c] = -1e30f;
            }
        }

        // ---- online softmax (row reductions over 16 tx lanes) ----
        float cc[8];
        #pragma unroll
        for (int r = 0; r < 8; r++) {
            float mx = fmaxf(fmaxf(p[r][0], p[r][1]), fmaxf(p[r][2], p[r][3]));
            mx = fmaxf(mx, __shfl_xor_sync(0xffffffffu, mx, 1, 16));
            mx = fmaxf(mx, __shfl_xor_sync(0xffffffffu, mx, 2, 16));
            mx = fmaxf(mx, __shfl_xor_sync(0xffffffffu, mx, 4, 16));
            mx = fmaxf(mx, __shfl_xor_sync(0xffffffffu, mx, 8, 16));
            const float mn = fmaxf(m[r], mx);
            cc[r] = __expf(m[r] - mn);
            l[r] *= cc[r];
            m[r] = mn;
        }
        #pragma unroll
        for (int rp = 0; rp < 4; rp++) {
            const u64 ccp = packpair(cc[2 * rp], cc[2 * rp + 1]);
            #pragma unroll
            for (int c = 0; c < 4; c++) acc2[rp][c] = fmul2(acc2[rp][c], ccp);
        }
        #pragma unroll
        for (int r = 0; r < 8; r++) {
            #pragma unroll
            for (int c = 0; c < 4; c++) p[r][c] = __expf(p[r][c] - m[r]);
            float rs = (p[r][0] + p[r][1]) + (p[r][2] + p[r][3]);
            rs += __shfl_xor_sync(0xffffffffu, rs, 1, 16);
            rs += __shfl_xor_sync(0xffffffffu, rs, 2, 16);
            rs += __shfl_xor_sync(0xffffffffu, rs, 4, 16);
            rs += __shfl_xor_sync(0xffffffffu, rs, 8, 16);
            l[r] += rs;
        }

        // ---- write P tile (conflict-free) ----
        #pragma unroll
        for (int r = 0; r < 8; r++)
            *(float4*)&Ps[(ty * 8 + r) * PS_STRIDE + tx * 4] =
                make_float4(p[r][0], p[r][1], p[r][2], p[r][3]);
        __syncthreads();

        // ---- PV: out += P @ V ----
        const float* PsT = Ps + ty * 8 * PS_STRIDE;
        #pragma unroll 4
        for (int j = 0; j < 64; j++) {
            float4 vv = *(const float4*)&Vs[j * KS_STRIDE + tx * 4];
            const u64 v0 = pack2(vv.x), v1 = pack2(vv.y);
            const u64 v2 = pack2(vv.z), v3 = pack2(vv.w);
            const float pr0 = PsT[0 * PS_STRIDE + j];
            const float pr1 = PsT[1 * PS_STRIDE + j];
            const float pr2 = PsT[2 * PS_STRIDE + j];
            const float pr3 = PsT[3 * PS_STRIDE + j];
            const float pr4 = PsT[4 * PS_STRIDE + j];
            const float pr5 = PsT[5 * PS_STRIDE + j];
            const float pr6 = PsT[6 * PS_STRIDE + j];
            const float pr7 = PsT[7 * PS_STRIDE + j];
            const u64 pA = packpair(pr0, pr1);
            const u64 pB = packpair(pr2, pr3);
            const u64 pC = packpair(pr4, pr5);
            const u64 pD = packpair(pr6, pr7);
            acc2[0][0] = ffma2(pA, v0, acc2[0][0]);  acc2[0][1] = ffma2(pA, v1, acc2[0][1]);
            acc2[0][2] = ffma2(pA, v2, acc2[0][2]);  acc2[0][3] = ffma2(pA, v3, acc2[0][3]);
            acc2[1][0] = ffma2(pB, v0, acc2[1][0]);  acc2[1][1] = ffma2(pB, v1, acc2[1][1]);
            acc2[1][2] = ffma2(pB, v2, acc2[1][2]);  acc2[1][3] = ffma2(pB, v3, acc2[1][3]);
            acc2[2][0] = ffma2(pC, v0, acc2[2][0]);  acc2[2][1] = ffma2(pC, v1, acc2[2][1]);
            acc2[2][2] = ffma2(pC, v2, acc2[2][2]);  acc2[2][3] = ffma2(pC, v3, acc2[2][3]);
            acc2[3][0] = ffma2(pD, v0, acc2[3][0]);  acc2[3][1] = ffma2(pD, v1, acc2[3][1]);
            acc2[3][2] = ffma2(pD, v2, acc2[3][2]);  acc2[3][3] = ffma2(pD, v3, acc2[3][3]);
        }
    }

    // ---- epilogue: normalize and write ----
    #pragma unroll
    for (int rp = 0; rp < 4; rp++) {
        const float inv0 = 1.f / l[2 * rp];
        const float inv1 = 1.f / l[2 * rp + 1];
        float o0[4], o1[4];
        #pragma unroll
        for (int c = 0; c < 4; c++) {
            float2 v = unpack2(acc2[rp][c]);
            o0[c] = v.x * inv0;
            o1[c] = v.y * inv1;
        }
        const size_t row0 = (size_t)(b * SS + qt * QT + ty * 8 + 2 * rp);
        float* dst0 = g_att + row0 * DD + h * DK + tx * 4;
        *(float4*)dst0        = make_float4(o0[0], o0[1], o0[2], o0[3]);
        *(float4*)(dst0 + DD) = make_float4(o1[0], o1[1], o1[2], o1[3]);
    }
}

// ---------------------------------------------------------------------------
// Launch
// ---------------------------------------------------------------------------
extern "C" void kernel_launch(void* const* d_in, const int* in_sizes, int n_in,
                              void* d_out, int out_size)
{
    const float* x  = (const float*)d_in[0];
    const float* Wq = (const float*)d_in[1];
    const float* bq = (const float*)d_in[2];
    const float* Wk = (const float*)d_in[3];
    const float* bk = (const float*)d_in[4];
    const float* Wv = (const float*)d_in[5];
    const float* bv = (const float*)d_in[6];
    const float* Wo = (const float*)d_in[7];
    const float* bo = (const float*)d_in[8];
    float* out = (float*)d_out;

    dim3 ggrid(DD / 128, MM / 64);   // (4, 128)

    gemm_bias_kernel<<<ggrid, 256>>>(x, Wq, bq, nullptr, 0);
    gemm_bias_kernel<<<ggrid, 256>>>(x, Wk, bk, nullptr, 1);
    gemm_bias_kernel<<<ggrid, 256>>>(x, Wv, bv, nullptr, 2);

    cudaFuncSetAttribute(attn_kernel,
                         cudaFuncAttributeMaxDynamicSharedMemorySize,
                         SMEM_ATTN);
    attn_kernel<<<dim3(SS / QT, HH, BB), 256, SMEM_ATTN>>>();

    gemm_bias_kernel<<<ggrid, 256>>>(nullptr, Wo, bo, out, 3);
}